// round 10
// baseline (speedup 1.0000x reference)
#include <cuda_runtime.h>
#include <cstdint>

// out[n] = S * ( sum_k (x[k]-X_ZP) * y[k,n]  -  Y_ZP * sum_k (x[k]-X_ZP) )
// Exact int32 accumulation. X_SCALE=0.0215, X_ZP=-25, Y_SCALE=0.0176, Y_ZP=18
//
// Fused single kernel (16 n-tiles x 64 K-splits) x 256 thr.
// Streaming phase = the 75us R5 gemv, UNTOUCHED. Publication is fence-free:
//   producer: stores -> __syncthreads -> ONE atom.add.release.gpu (tid 0)
//   consumer: tid 0 polls ld.acquire.gpu (+nanosleep) -> __syncthreads
// (standard release/acquire split-K pattern; no MEMBAR in the hot path —
//  R7's +8us was 262K per-thread __threadfence calls).
// Last 4 blocks per tile become reducers (64 chip-wide, overlapping the
// stream's straggler tail). Counters self-reset for graph replay.

#define KDIM 8192
#define NDIM 16384
#define THREADS 256
#define COLS_PER_THREAD 4
#define COLS_PER_BLOCK (THREADS * COLS_PER_THREAD)    // 1024
#define N_TILES (NDIM / COLS_PER_BLOCK)               // 16
#define KCHUNK 128
#define SPLITS (KDIM / KCHUNK)                        // 64
#define REDUCERS_PER_TILE 4
#define COLS_PER_REDUCER (COLS_PER_BLOCK / REDUCERS_PER_TILE)  // 256

__device__ int g_part[SPLITS][NDIM];    // per-split partials
__device__ unsigned g_tick[N_TILES];    // streaming-done tickets (release)
__device__ unsigned g_fin[N_TILES];     // reducer-done tickets

__device__ __forceinline__ unsigned atom_add_release_gpu(unsigned* p, unsigned v) {
    unsigned r;
    asm volatile("atom.add.release.gpu.global.u32 %0, [%1], %2;"
                 : "=r"(r) : "l"(p), "r"(v) : "memory");
    return r;
}
__device__ __forceinline__ unsigned ld_acquire_gpu(const unsigned* p) {
    unsigned r;
    asm volatile("ld.acquire.gpu.global.u32 %0, [%1];"
                 : "=r"(r) : "l"(p) : "memory");
    return r;
}

__global__ __launch_bounds__(THREADS, 8) void gemv_fused_kernel(
    const int* __restrict__ x, const int* __restrict__ y,
    float* __restrict__ out)
{
    __shared__ int sa[KCHUNK];
    __shared__ unsigned s_ticket;
    __shared__ int s_warp[THREADS / 32];

    const int tid   = threadIdx.x;
    const int tile  = blockIdx.x;
    const int split = blockIdx.y;
    const int k0    = split * KCHUNK;

    // a[k] = x[k] - X_ZP = x[k] + 25
    if (tid < KCHUNK)
        sa[tid] = x[k0 + tid] + 25;
    __syncthreads();

    const int n0 = tile * COLS_PER_BLOCK + tid * COLS_PER_THREAD;
    const int4* yp = reinterpret_cast<const int4*>(y + (size_t)k0 * NDIM + n0);
    const size_t strideV = NDIM / 4;

    int a0 = 0, a1 = 0, a2 = 0, a3 = 0;
    #pragma unroll 8
    for (int kk = 0; kk < KCHUNK; kk++) {
        const int a = sa[kk];
        const int4 v = __ldcs(&yp[(size_t)kk * strideV]);
        a0 += a * v.x;  a1 += a * v.y;  a2 += a * v.z;  a3 += a * v.w;
    }

    *reinterpret_cast<int4*>(&g_part[split][n0]) = make_int4(a0, a1, a2, a3);

    // Publish: block-wide stores ordered by __syncthreads, then ONE
    // release-scoped ticket increment. No per-thread fence.
    __syncthreads();
    if (tid == 0)
        s_ticket = atom_add_release_gpu(&g_tick[tile], 1u);
    __syncthreads();
    const unsigned ticket = s_ticket;
    if (ticket < SPLITS - REDUCERS_PER_TILE) return;

    // ---- Reducer path (last 4 blocks of this tile) ----
    const int quarter = (int)ticket - (SPLITS - REDUCERS_PER_TILE);  // 0..3

    // Zero-point correction (independent of partials; fills the wait):
    int sx = 0;
    #pragma unroll
    for (int i = 0; i < KDIM / THREADS; i++)
        sx += __ldg(&x[tid + i * THREADS]);
    #pragma unroll
    for (int o = 16; o > 0; o >>= 1)
        sx += __shfl_down_sync(0xffffffffu, sx, o);
    if ((tid & 31) == 0) s_warp[tid >> 5] = sx;
    __syncthreads();
    int sum_a = 25 * KDIM;
    #pragma unroll
    for (int w = 0; w < THREADS / 32; w++) sum_a += s_warp[w];

    // Wait for all 64 splits of this tile (acquire).
    if (tid == 0) {
        while (ld_acquire_gpu(&g_tick[tile]) < SPLITS) __nanosleep(64);
    }
    __syncthreads();   // propagate tid0's acquire to the block

    // Reduce: one column per thread, 64 splits, 4 independent chains.
    const int col = tile * COLS_PER_BLOCK + quarter * COLS_PER_REDUCER + tid;
    int r0 = 0, r1 = 0, r2 = 0, r3 = 0;
    #pragma unroll
    for (int s = 0; s < SPLITS; s += 4) {
        r0 += g_part[s + 0][col];
        r1 += g_part[s + 1][col];
        r2 += g_part[s + 2][col];
        r3 += g_part[s + 3][col];
    }
    const int acc = (r0 + r1) + (r2 + r3);

    const float S = (float)(0.0215 * 0.0176);
    out[col] = S * (float)(acc - 18 * sum_a);

    // Self-reset for the next graph replay (last reducer of the tile).
    __syncthreads();
    if (tid == 0) {
        unsigned f = atom_add_release_gpu(&g_fin[tile], 1u);
        if (f == REDUCERS_PER_TILE - 1) {
            g_fin[tile]  = 0;
            g_tick[tile] = 0;
            __threadfence();   // cold path: once per tile per run
        }
    }
}

extern "C" void kernel_launch(void* const* d_in, const int* in_sizes, int n_in,
                              void* d_out, int out_size) {
    const int* x = (const int*)d_in[0];   // [K]
    const int* y = (const int*)d_in[1];   // [K, N]
    float* out = (float*)d_out;           // [N]

    dim3 grid(N_TILES, SPLITS);
    gemv_fused_kernel<<<grid, THREADS>>>(x, y, out);
}

// round 11
// speedup vs baseline: 1.0042x; 1.0042x over previous
#include <cuda_runtime.h>
#include <cstdint>

// out[n] = S * ( sum_k (x[k]-X_ZP) * y[k,n]  -  Y_ZP * sum_k (x[k]-X_ZP) )
// Exact int32 accumulation. X_SCALE=0.0215, X_ZP=-25, Y_SCALE=0.0176, Y_ZP=18
//
// Fused single kernel, (16 n-tiles x 64 K-splits) x 256 thr, single wave.
// Streaming phase = the 75us R5 gemv, untouched. After release-publishing
// its partial, EVERY block waits on its tile's counter and then reduces its
// own 16 columns (1024-way parallel tail over 4 MB of L2-resident partials
// -> ~1us instead of R10's 7.8us 64-block tail).
// Per-tile g_sa[tile][split] so the tile counter orders the correction sums.

#define KDIM 8192
#define NDIM 16384
#define THREADS 256
#define COLS_PER_THREAD 4
#define COLS_PER_BLOCK (THREADS * COLS_PER_THREAD)    // 1024
#define N_TILES (NDIM / COLS_PER_BLOCK)               // 16
#define KCHUNK 128
#define SPLITS (KDIM / KCHUNK)                        // 64
#define RED_COLS 16                                   // cols reduced per block
#define RED_SEGS 16                                   // split-segments (64/4)

__device__ int g_part[SPLITS][NDIM];       // per-split partials
__device__ int g_sa[N_TILES][SPLITS];      // per-tile per-split sum of (x+25)
__device__ unsigned g_tick[N_TILES];       // streaming-done tickets
__device__ unsigned g_fin[N_TILES];        // reduction-done tickets

__device__ __forceinline__ unsigned atom_add_release_gpu(unsigned* p, unsigned v) {
    unsigned r;
    asm volatile("atom.add.release.gpu.global.u32 %0, [%1], %2;"
                 : "=r"(r) : "l"(p), "r"(v) : "memory");
    return r;
}
__device__ __forceinline__ unsigned ld_acquire_gpu(const unsigned* p) {
    unsigned r;
    asm volatile("ld.acquire.gpu.global.u32 %0, [%1];"
                 : "=r"(r) : "l"(p) : "memory");
    return r;
}

__global__ __launch_bounds__(THREADS, 8) void gemv_fused_kernel(
    const int* __restrict__ x, const int* __restrict__ y,
    float* __restrict__ out)
{
    __shared__ int sa[KCHUNK];
    __shared__ int s_red[RED_SEGS][RED_COLS];
    __shared__ int s_sa;

    const int tid   = threadIdx.x;
    const int tile  = blockIdx.x;
    const int split = blockIdx.y;
    const int k0    = split * KCHUNK;

    // a[k] = x[k] - X_ZP = x[k] + 25
    if (tid < KCHUNK)
        sa[tid] = x[k0 + tid] + 25;
    __syncthreads();

    const int n0 = tile * COLS_PER_BLOCK + tid * COLS_PER_THREAD;
    const int4* yp = reinterpret_cast<const int4*>(y + (size_t)k0 * NDIM + n0);
    const size_t strideV = NDIM / 4;

    int a0 = 0, a1 = 0, a2 = 0, a3 = 0;
    #pragma unroll 8
    for (int kk = 0; kk < KCHUNK; kk++) {
        const int a = sa[kk];
        const int4 v = __ldcs(&yp[(size_t)kk * strideV]);
        a0 += a * v.x;  a1 += a * v.y;  a2 += a * v.z;  a3 += a * v.w;
    }

    *reinterpret_cast<int4*>(&g_part[split][n0]) = make_int4(a0, a1, a2, a3);

    // This tile's x-chunk sum (ordered by the same ticket as the partials).
    if (tid < 32) {
        int s = (sa[tid] + sa[tid + 32]) + (sa[tid + 64] + sa[tid + 96]);
        #pragma unroll
        for (int o = 16; o > 0; o >>= 1)
            s += __shfl_down_sync(0xffffffffu, s, o);
        if (tid == 0) g_sa[tile][split] = s;
    }

    // Publish: block-wide stores ordered by __syncthreads, then ONE
    // release-scoped ticket increment.
    __syncthreads();
    if (tid == 0) {
        atom_add_release_gpu(&g_tick[tile], 1u);
        // Spin until all 64 splits of this tile have published (short:
        // single wave, all blocks finish streaming nearly together).
        while (ld_acquire_gpu(&g_tick[tile]) < SPLITS) __nanosleep(32);
    }
    __syncthreads();   // propagate tid0's acquire to the block

    // ---- Reduction: this block owns 16 columns of its tile ----
    // correction: sum over this tile's 64 split sums
    if (tid < 32) {
        int s = g_sa[tile][tid] + g_sa[tile][tid + 32];
        #pragma unroll
        for (int o = 16; o > 0; o >>= 1)
            s += __shfl_down_sync(0xffffffffu, s, o);
        if (tid == 0) s_sa = s;
    }

    const int c   = tid & (RED_COLS - 1);          // 0..15
    const int seg = tid >> 4;                      // 0..15 (4 splits each)
    const int col = tile * COLS_PER_BLOCK + split * RED_COLS + c;

    int r0 = g_part[seg * 4 + 0][col];
    int r1 = g_part[seg * 4 + 1][col];
    int r2 = g_part[seg * 4 + 2][col];
    int r3 = g_part[seg * 4 + 3][col];
    s_red[seg][c] = (r0 + r1) + (r2 + r3);
    __syncthreads();

    if (tid < RED_COLS) {
        int acc = 0;
        #pragma unroll
        for (int s = 0; s < RED_SEGS; s++)
            acc += s_red[s][tid];

        const float S = (float)(0.0215 * 0.0176);
        out[tile * COLS_PER_BLOCK + split * RED_COLS + tid] =
            S * (float)(acc - 18 * s_sa);
    }

    // Self-reset for the next graph replay: last finishing block of the tile.
    __syncthreads();
    if (tid == 0) {
        unsigned f = atom_add_release_gpu(&g_fin[tile], 1u);
        if (f == SPLITS - 1) {
            g_fin[tile]  = 0;
            g_tick[tile] = 0;
            __threadfence();   // cold path: once per tile per run
        }
    }
}

extern "C" void kernel_launch(void* const* d_in, const int* in_sizes, int n_in,
                              void* d_out, int out_size) {
    const int* x = (const int*)d_in[0];   // [K]
    const int* y = (const int*)d_in[1];   // [K, N]
    float* out = (float*)d_out;           // [N]

    dim3 grid(N_TILES, SPLITS);
    gemv_fused_kernel<<<grid, THREADS>>>(x, y, out);
}